// round 7
// baseline (speedup 1.0000x reference)
#include <cuda_runtime.h>
#include <cuda_fp16.h>
#include <cstdint>
#include <math.h>

#define D       128
#define NMAX    32768
#define KPAD    10112                 // 158 tiles * 64
#define NTILE   (KPAD / 64)           // 158
#define NSEG1   8                     // stage-1 segments
#define NSEG2   4                     // stage-2 segments
#define LO_SCALE   4096.0f
#define LO_INV     (1.0f / 4096.0f)

// ---------------- scratch ----------------------------------------------------
__device__ float g_halfnorm[KPAD];
__device__ int   g_bestidx[NMAX];
__device__ unsigned long long g_best2[NMAX];   // stage-2 packed results
__device__ float g_counts[KPAD];
__device__ float g_sums[KPAD * D];
__device__ float g_newmean[KPAD * D];
__device__ float g_scalars[2];
__device__ float g_xh2[NMAX], g_xl2[NMAX];     // per-row split norms
__device__ int   g_maxE2, g_maxEl2;            // max centroid norms (as int-float)
__device__ int   g_ucount;                     // # uncertain rows
__device__ int   g_ulist[NMAX];
__device__ int   g_upos[NMAX];

// fragment-ordered fp16 operands
__device__ __align__(16) uint4 g_ah4[(NMAX / 16) * 8 * 32];   // A hi
__device__ __align__(16) uint4 g_al4[(NMAX / 16) * 8 * 32];   // A lo
__device__ __align__(16) uint4 g_bf4[(KPAD / 8) * 8 * 32];    // B full {h0,h1,l0,l1}
__device__ __align__(16) uint4 g_bs1[NTILE * 8 * 32 * 4];     // B hi-only, nf-paired
// stage-2 compacted A fragments
__device__ __align__(16) uint4 g_a2h[(NMAX / 16) * 8 * 32];
__device__ __align__(16) uint4 g_a2l[(NMAX / 16) * 8 * 32];
// stage-1 per-chain top2: [row][64 chains] of {s1,j1,s2,j2}
__device__ __align__(16) uint4 g_chains[NMAX * 64];

// ---------------- helpers ----------------------------------------------------
__device__ __forceinline__ uint32_t smem_to_u32(const void* p) {
    uint32_t a;
    asm("{ .reg .u64 t; cvta.to.shared.u64 t, %1; cvt.u32.u64 %0, t; }"
        : "=r"(a) : "l"(p));
    return a;
}
__device__ __forceinline__ unsigned long long cvta_g(const void* p) {
    unsigned long long r;
    asm("cvta.to.global.u64 %0, %1;" : "=l"(r) : "l"(p));
    return r;
}
__device__ __forceinline__ void cp_async16(uint32_t dst, const void* src) {
    asm volatile("cp.async.cg.shared.global [%0], [%1], 16;"
                 :: "r"(dst), "l"(cvta_g(src)) : "memory");
}
#define CP_COMMIT() asm volatile("cp.async.commit_group;" ::: "memory")
#define CP_WAIT1()  asm volatile("cp.async.wait_group 1;" ::: "memory")
#define GROUP_BAR(g) asm volatile("bar.sync %0, 256;" :: "r"((g) + 1) : "memory")

#define MMA16(d, a, b0, b1) \
    asm volatile("mma.sync.aligned.m16n8k16.row.col.f32.f16.f16.f32 " \
        "{%0,%1,%2,%3},{%4,%5,%6,%7},{%8,%9},{%0,%1,%2,%3};" \
        : "+f"((d)[0]), "+f"((d)[1]), "+f"((d)[2]), "+f"((d)[3]) \
        : "r"((a).x), "r"((a).y), "r"((a).z), "r"((a).w), \
          "r"(b0), "r"(b1))

__device__ __forceinline__ unsigned long long pack_cand(float s, int j) {
    uint32_t u = __float_as_uint(s);
    u = (u & 0x80000000u) ? ~u : (u | 0x80000000u);
    return ((unsigned long long)u << 32) | (uint32_t)(~j);
}
__device__ __forceinline__ uint32_t h2pack(float a, float b) {
    __half2 h = __halves2half2(__float2half_rn(a), __float2half_rn(b));
    return *reinterpret_cast<uint32_t*>(&h);
}
__device__ __forceinline__ float hi_of(float x) {
    return __half2float(__float2half_rn(x));
}
__device__ __forceinline__ float blockReduceSum(float v) {
    __shared__ float sh[32];
    int lane = threadIdx.x & 31, wid = threadIdx.x >> 5;
    #pragma unroll
    for (int o = 16; o > 0; o >>= 1) v += __shfl_down_sync(0xffffffffu, v, o);
    if (lane == 0) sh[wid] = v;
    __syncthreads();
    int nw = (blockDim.x + 31) >> 5;
    v = (wid == 0 && lane < nw) ? sh[lane] : 0.0f;
    if (wid == 0) {
        #pragma unroll
        for (int o = 16; o > 0; o >>= 1) v += __shfl_down_sync(0xffffffffu, v, o);
    }
    return v;
}
__device__ __forceinline__ bool better(float sa, int ja, float sb, int jb) {
    return (sa > sb) || (sa == sb && ja < jb);
}

// ---------------- prep kernels -----------------------------------------------
__global__ void zero_kernel() {
    int i = blockIdx.x * blockDim.x + threadIdx.x;
    if (i < KPAD) g_counts[i] = 0.0f;
    if (i < 2)    g_scalars[i] = 0.0f;
    if (i < NMAX) g_best2[i] = 0ull;
    if (i == 0) { g_ucount = 0; g_maxE2 = 0; g_maxEl2 = 0; }
    int stride = gridDim.x * blockDim.x;
    for (int e = i; e < KPAD * D; e += stride) g_sums[e] = 0.0f;
}
// per-centroid half-norm + global max norms
__global__ void halfnorm_kernel(const float* __restrict__ E, int K) {
    int w    = (blockIdx.x * blockDim.x + threadIdx.x) >> 5;
    int lane = threadIdx.x & 31;
    if (w >= KPAD) return;
    if (w >= K) { if (lane == 0) g_halfnorm[w] = INFINITY; return; }
    const float4* row = (const float4*)(E + (size_t)w * D);
    float4 v = row[lane];
    float s = v.x * v.x + v.y * v.y + v.z * v.z + v.w * v.w;
    float hx = hi_of(v.x), hy = hi_of(v.y), hz = hi_of(v.z), hw = hi_of(v.w);
    float lx = v.x - hx, ly = v.y - hy, lz = v.z - hz, lw = v.w - hw;
    float sl = lx * lx + ly * ly + lz * lz + lw * lw;
    #pragma unroll
    for (int o = 16; o > 0; o >>= 1) {
        s  += __shfl_down_sync(0xffffffffu, s, o);
        sl += __shfl_down_sync(0xffffffffu, sl, o);
    }
    if (lane == 0) {
        g_halfnorm[w] = 0.5f * s;
        atomicMax(&g_maxE2,  __float_as_int(s));
        atomicMax(&g_maxEl2, __float_as_int(sl));
    }
}
// per-row split norms of X
__global__ void norms_x(const float* __restrict__ X) {
    int w    = (blockIdx.x * blockDim.x + threadIdx.x) >> 5;
    int lane = threadIdx.x & 31;
    if (w >= NMAX) return;
    float4 v = ((const float4*)(X + (size_t)w * D))[lane];
    float hx = hi_of(v.x), hy = hi_of(v.y), hz = hi_of(v.z), hw = hi_of(v.w);
    float lx = v.x - hx, ly = v.y - hy, lz = v.z - hz, lw = v.w - hw;
    float sh2 = hx * hx + hy * hy + hz * hz + hw * hw;
    float sl2 = lx * lx + ly * ly + lz * lz + lw * lw;
    #pragma unroll
    for (int o = 16; o > 0; o >>= 1) {
        sh2 += __shfl_down_sync(0xffffffffu, sh2, o);
        sl2 += __shfl_down_sync(0xffffffffu, sl2, o);
    }
    if (lane == 0) { g_xh2[w] = sqrtf(sh2); g_xl2[w] = sqrtf(sl2); }
}
__global__ void prep_a(const float* __restrict__ X) {
    int t = blockIdx.x * blockDim.x + threadIdx.x;
    if (t >= (NMAX / 16) * 256) return;
    int lane = t & 31, kc = (t >> 5) & 7, mg = t >> 8;
    int r0 = mg * 16 + (lane >> 2);
    int c0 = kc * 16 + (lane & 3) * 2;
    const float* p0 = X + (size_t)r0 * D + c0;
    const float* p1 = X + (size_t)(r0 + 8) * D + c0;
    float x00 = p0[0], x01 = p0[1], x02 = p0[8], x03 = p0[9];
    float x10 = p1[0], x11 = p1[1], x12 = p1[8], x13 = p1[9];
    float h00 = hi_of(x00), h01 = hi_of(x01), h02 = hi_of(x02), h03 = hi_of(x03);
    float h10 = hi_of(x10), h11 = hi_of(x11), h12 = hi_of(x12), h13 = hi_of(x13);
    uint4 hi, lo;
    hi.x = h2pack(h00, h01); hi.y = h2pack(h10, h11);
    hi.z = h2pack(h02, h03); hi.w = h2pack(h12, h13);
    lo.x = h2pack((x00 - h00) * LO_SCALE, (x01 - h01) * LO_SCALE);
    lo.y = h2pack((x10 - h10) * LO_SCALE, (x11 - h11) * LO_SCALE);
    lo.z = h2pack((x02 - h02) * LO_SCALE, (x03 - h03) * LO_SCALE);
    lo.w = h2pack((x12 - h12) * LO_SCALE, (x13 - h13) * LO_SCALE);
    g_ah4[t] = hi;
    g_al4[t] = lo;
}
// B: full fragments (stage2) + hi-only nf-paired layout (stage1)
__global__ void prep_b(const float* __restrict__ E, int K) {
    int t = blockIdx.x * blockDim.x + threadIdx.x;
    if (t >= (KPAD / 8) * 256) return;
    int lane = t & 31, kc = (t >> 5) & 7, ng = t >> 8;
    int j = ng * 8 + (lane >> 2);
    int k0 = kc * 16 + (lane & 3) * 2;
    float b0 = 0.f, b1 = 0.f, b2 = 0.f, b3 = 0.f;
    if (j < K) {
        const float* p = E + (size_t)j * D + k0;
        b0 = p[0]; b1 = p[1]; b2 = p[8]; b3 = p[9];
    }
    float g0 = hi_of(b0), g1 = hi_of(b1), g2 = hi_of(b2), g3 = hi_of(b3);
    uint4 v;
    v.x = h2pack(g0, g1);
    v.y = h2pack(g2, g3);
    v.z = h2pack((b0 - g0) * LO_SCALE, (b1 - g1) * LO_SCALE);
    v.w = h2pack((b2 - g2) * LO_SCALE, (b3 - g3) * LO_SCALE);
    g_bf4[t] = v;
    // stage1 layout: [tile][kc][lane][jp] uint4, halves = nf parity
    int tile = ng >> 3, nfq = ng & 7, jp = nfq >> 1, half = nfq & 1;
    int idx4 = ((tile * 8 + kc) * 32 + lane) * 4 + jp;
    ((uint2*)g_bs1)[idx4 * 2 + half] = make_uint2(v.x, v.y);
}

// ---------------- stage 1: hi-only approx argmin with top-2 chains -----------
// 512 thr = 2 groups x 8 warps; warp tile 32x64 (mf2 x nf8); M=256/CTA.
#define S1_OFF_B   65536
#define S1_OFF_HS  (S1_OFF_B + 4 * 16384)
#define S1_SMEM    (S1_OFF_HS + 4 * 256)

__device__ __forceinline__ void issue_tile_s1(uint32_t sb, int slot, int t, int ltid) {
    const uint4* src = g_bs1 + (size_t)t * 1024;
    uint32_t dB = sb + S1_OFF_B + slot * 16384;
    #pragma unroll
    for (int i = 0; i < 4; i++) {
        int idx = ltid + i * 256;
        cp_async16(dB + idx * 16, src + idx);
    }
    if (ltid < 16)
        cp_async16(sb + S1_OFF_HS + slot * 256 + ltid * 16,
                   g_halfnorm + t * 64 + ltid * 4);
}

__global__ __launch_bounds__(512, 1)
void argmin_approx() {
    extern __shared__ char smem[];
    uint32_t sb = smem_to_u32(smem);
    const int tid   = threadIdx.x;
    const int gid   = tid >> 8;
    const int ltid  = tid & 255;
    const int lane  = tid & 31;
    const int mwarp = (tid >> 5) & 7;
    const int rt  = blockIdx.x >> 3;
    const int seg = blockIdx.x & 7;
    const int tb = (seg * NTILE) / NSEG1;
    const int te = ((seg + 1) * NTILE) / NSEG1;
    const int t0 = tb + gid;
    const int rowbase = rt * 256;

    // prologue: A hi (64KB) + first tiles
    {
        const uint4* srcA = g_ah4 + (size_t)rt * 4096;
        #pragma unroll
        for (int i = 0; i < 8; i++) {
            int idx = tid + i * 512;
            cp_async16(sb + idx * 16, srcA + idx);
        }
        if (t0 < te) issue_tile_s1(sb, gid * 2, t0, ltid);
        CP_COMMIT();
        if (t0 + 2 < te) issue_tile_s1(sb, gid * 2 + 1, t0 + 2, ltid);
        CP_COMMIT();
        CP_WAIT1();
        __syncthreads();
    }

    const uint4* As = (const uint4*)smem;

    float b1v[4], b2v[4]; int j1v[4], j2v[4];
    #pragma unroll
    for (int q = 0; q < 4; q++) { b1v[q] = -INFINITY; b2v[q] = -INFINITY; j1v[q] = 0; j2v[q] = 0; }

    int s = 0;
    for (int t = t0; t < te; t += 2, s ^= 1) {
        const int slot = gid * 2 + s;
        const uint4* Bs = (const uint4*)(smem + S1_OFF_B + slot * 16384);

        float acc[2][8][4];
        #pragma unroll
        for (int mf = 0; mf < 2; mf++)
            #pragma unroll
            for (int nf = 0; nf < 8; nf++)
                #pragma unroll
                for (int e = 0; e < 4; e++) acc[mf][nf][e] = 0.0f;

        #pragma unroll
        for (int kc = 0; kc < 8; kc++) {
            uint4 a[2];
            #pragma unroll
            for (int mf = 0; mf < 2; mf++)
                a[mf] = As[((mwarp * 2 + mf) * 8 + kc) * 32 + lane];
            uint4 bv[4];
            #pragma unroll
            for (int jp = 0; jp < 4; jp++)
                bv[jp] = Bs[(kc * 32 + lane) * 4 + jp];
            #pragma unroll
            for (int jp = 0; jp < 4; jp++)
                #pragma unroll
                for (int mf = 0; mf < 2; mf++) {
                    MMA16(acc[mf][2 * jp],     a[mf], bv[jp].x, bv[jp].y);
                    MMA16(acc[mf][2 * jp + 1], a[mf], bv[jp].z, bv[jp].w);
                }
        }

        // epilogue: top-2 per chain (j ascending within chain)
        const float* Hsf = (const float*)(smem + S1_OFF_HS + slot * 256);
        #pragma unroll
        for (int nf = 0; nf < 8; nf++) {
            int cl = nf * 8 + (lane & 3) * 2;
            float hn0 = Hsf[cl], hn1 = Hsf[cl + 1];
            int j0 = t * 64 + cl;
            #pragma unroll
            for (int mf = 0; mf < 2; mf++) {
                #pragma unroll
                for (int rh = 0; rh < 2; rh++) {
                    int q = mf * 2 + rh;
                    float s0 = acc[mf][nf][rh * 2]     - hn0;
                    float s1 = acc[mf][nf][rh * 2 + 1] - hn1;
                    if (s0 > b1v[q]) { b2v[q] = b1v[q]; j2v[q] = j1v[q]; b1v[q] = s0; j1v[q] = j0; }
                    else if (s0 > b2v[q]) { b2v[q] = s0; j2v[q] = j0; }
                    if (s1 > b1v[q]) { b2v[q] = b1v[q]; j2v[q] = j1v[q]; b1v[q] = s1; j1v[q] = j0 + 1; }
                    else if (s1 > b2v[q]) { b2v[q] = s1; j2v[q] = j0 + 1; }
                }
            }
        }

        GROUP_BAR(gid);
        if (t + 4 < te) issue_tile_s1(sb, slot, t + 4, ltid);
        CP_COMMIT();
        CP_WAIT1();
        GROUP_BAR(gid);
    }

    // write chains
    int chain = seg * 8 + gid * 4 + (lane & 3);
    #pragma unroll
    for (int q = 0; q < 4; q++) {
        int mf = q >> 1, rh = q & 1;
        int row = rowbase + mwarp * 32 + mf * 16 + rh * 8 + (lane >> 2);
        g_chains[(size_t)row * 64 + chain] =
            make_uint4(__float_as_uint(b1v[q]), (uint32_t)j1v[q],
                       __float_as_uint(b2v[q]), (uint32_t)j2v[q]);
    }
}

// ---------------- reduce: exact top-2 per row, margin test -------------------
__device__ __forceinline__ void merge2(float& a1, int& i1, float& a2, int& i2,
                                       float c1, int k1, float c2, int k2) {
    if (better(c1, k1, a1, i1)) {
        float n2; int m2;
        if (better(a1, i1, c2, k2)) { n2 = a1; m2 = i1; } else { n2 = c2; m2 = k2; }
        a1 = c1; i1 = k1; a2 = n2; i2 = m2;
    } else if (better(c1, k1, a2, i2)) {
        a2 = c1; i2 = k1;
    }
}
__global__ void reduce_rows() {
    int w    = (blockIdx.x * blockDim.x + threadIdx.x) >> 5;
    int lane = threadIdx.x & 31;
    if (w >= NMAX) return;
    const uint4* ch = g_chains + (size_t)w * 64;
    uint4 e0 = ch[lane], e1 = ch[lane + 32];
    float a1 = __uint_as_float(e0.x), a2 = __uint_as_float(e0.z);
    int   i1 = (int)e0.y,             i2 = (int)e0.w;
    merge2(a1, i1, a2, i2, __uint_as_float(e1.x), (int)e1.y,
                           __uint_as_float(e1.z), (int)e1.w);
    #pragma unroll
    for (int o = 16; o > 0; o >>= 1) {
        float c1 = __shfl_xor_sync(0xffffffffu, a1, o);
        int   k1 = __shfl_xor_sync(0xffffffffu, i1, o);
        float c2 = __shfl_xor_sync(0xffffffffu, a2, o);
        int   k2 = __shfl_xor_sync(0xffffffffu, i2, o);
        merge2(a1, i1, a2, i2, c1, k1, c2, k2);
    }
    if (lane == 0) {
        float Me  = sqrtf(__int_as_float(g_maxE2));
        float Mel = sqrtf(__int_as_float(g_maxEl2));
        float margin = 1.02f * (g_xl2[w] * Me + g_xh2[w] * Mel)
                     + 2e-5f * g_xh2[w] * Me + 1e-3f;
        g_bestidx[w] = i1;
        if (a2 >= a1 - 2.0f * margin) {
            int pos = atomicAdd(&g_ucount, 1);
            g_ulist[pos] = w;
            g_upos[w] = pos;
        } else {
            g_upos[w] = -1;
        }
    }
}

// ---------------- stage 2 prep: gather uncertain-row fragments ---------------
__global__ void prep_a2(const float* __restrict__ X) {
    int b = blockIdx.x;                 // = mg of compact layout
    int u = g_ucount;
    int up = (u + 127) & ~127;
    if (b * 16 >= up) return;
    int tid = threadIdx.x;
    int lane = tid & 31, kc = (tid >> 5) & 7;
    int t = b * 256 + tid;
    int i0 = b * 16 + (lane >> 2);
    int i1 = i0 + 8;
    int r0 = (i0 < u) ? g_ulist[i0] : 0;
    int r1 = (i1 < u) ? g_ulist[i1] : 0;
    int c0 = kc * 16 + (lane & 3) * 2;
    const float* p0 = X + (size_t)r0 * D + c0;
    const float* p1 = X + (size_t)r1 * D + c0;
    float x00 = p0[0], x01 = p0[1], x02 = p0[8], x03 = p0[9];
    float x10 = p1[0], x11 = p1[1], x12 = p1[8], x13 = p1[9];
    float h00 = hi_of(x00), h01 = hi_of(x01), h02 = hi_of(x02), h03 = hi_of(x03);
    float h10 = hi_of(x10), h11 = hi_of(x11), h12 = hi_of(x12), h13 = hi_of(x13);
    uint4 hi, lo;
    hi.x = h2pack(h00, h01); hi.y = h2pack(h10, h11);
    hi.z = h2pack(h02, h03); hi.w = h2pack(h12, h13);
    lo.x = h2pack((x00 - h00) * LO_SCALE, (x01 - h01) * LO_SCALE);
    lo.y = h2pack((x10 - h10) * LO_SCALE, (x11 - h11) * LO_SCALE);
    lo.z = h2pack((x02 - h02) * LO_SCALE, (x03 - h03) * LO_SCALE);
    lo.w = h2pack((x12 - h12) * LO_SCALE, (x13 - h13) * LO_SCALE);
    g_a2h[t] = hi;
    g_a2l[t] = lo;
}

// ---------------- stage 2: exact (3-MMA) argmin on compacted rows ------------
#define OFF_AL  32768
#define OFF_B   65536
#define OFF_HS  196608
#define SMEM_SZ 197632

__device__ __forceinline__ void issue_tile(uint32_t sb, int slot, int t, int ltid) {
    const uint4* src = g_bf4 + (size_t)t * 2048;
    uint32_t dB = sb + OFF_B + slot * 32768;
    #pragma unroll
    for (int i = 0; i < 8; i++) {
        int idx = ltid + i * 256;
        cp_async16(dB + idx * 16, src + idx);
    }
    if (ltid < 16)
        cp_async16(sb + OFF_HS + slot * 256 + ltid * 16,
                   g_halfnorm + t * 64 + ltid * 4);
}

__global__ __launch_bounds__(512, 1)
void argmin_exact() {
    int u = g_ucount;
    int up = (u + 127) & ~127;
    const int rt  = blockIdx.x >> 2;
    if (rt * 128 >= up) return;
    extern __shared__ char smem[];
    uint32_t sb = smem_to_u32(smem);
    const int tid   = threadIdx.x;
    const int gid   = tid >> 8;
    const int ltid  = tid & 255;
    const int lane  = tid & 31;
    const int lwid  = (tid >> 5) & 7;
    const int mwarp = lwid >> 1, nwarp = lwid & 1;
    const int seg = blockIdx.x & 3;
    const int tb = (seg * NTILE) / NSEG2;
    const int te = ((seg + 1) * NTILE) / NSEG2;
    const int t0 = tb + gid;

    {
        const uint4* srcH = g_a2h + (size_t)rt * 2048;
        const uint4* srcL = g_a2l + (size_t)rt * 2048;
        #pragma unroll
        for (int i = 0; i < 4; i++) {
            int idx = tid + i * 512;
            cp_async16(sb + idx * 16, srcH + idx);
            cp_async16(sb + OFF_AL + idx * 16, srcL + idx);
        }
        if (t0 < te) issue_tile(sb, gid * 2, t0, ltid);
        CP_COMMIT();
        if (t0 + 2 < te) issue_tile(sb, gid * 2 + 1, t0 + 2, ltid);
        CP_COMMIT();
        CP_WAIT1();
        __syncthreads();
    }

    const uint4* AsH = (const uint4*)smem;
    const uint4* AsL = (const uint4*)(smem + OFF_AL);

    float best[4]; int bidx[4];
    #pragma unroll
    for (int r = 0; r < 4; r++) { best[r] = -INFINITY; bidx[r] = 0; }

    int s = 0;
    for (int t = t0; t < te; t += 2, s ^= 1) {
        const int slot = gid * 2 + s;
        const uint4* Bs = (const uint4*)(smem + OFF_B + slot * 32768);

        float accH[2][4][4], accC[2][4][4];
        #pragma unroll
        for (int mf = 0; mf < 2; mf++)
            #pragma unroll
            for (int nf = 0; nf < 4; nf++)
                #pragma unroll
                for (int e = 0; e < 4; e++) { accH[mf][nf][e] = 0.0f; accC[mf][nf][e] = 0.0f; }

        #pragma unroll
        for (int kc = 0; kc < 8; kc++) {
            uint4 ah[2], al[2];
            #pragma unroll
            for (int mf = 0; mf < 2; mf++) {
                int idx = ((mwarp * 2 + mf) * 8 + kc) * 32 + lane;
                ah[mf] = AsH[idx];
                al[mf] = AsL[idx];
            }
            uint4 bv[4];
            #pragma unroll
            for (int nf = 0; nf < 4; nf++)
                bv[nf] = Bs[((nwarp * 4 + nf) * 8 + kc) * 32 + lane];
            #pragma unroll
            for (int mf = 0; mf < 2; mf++)
                #pragma unroll
                for (int nf = 0; nf < 4; nf++) {
                    MMA16(accH[mf][nf], ah[mf], bv[nf].x, bv[nf].y);
                    MMA16(accC[mf][nf], ah[mf], bv[nf].z, bv[nf].w);
                    MMA16(accC[mf][nf], al[mf], bv[nf].x, bv[nf].y);
                }
        }

        const float* Hsf = (const float*)(smem + OFF_HS + slot * 256);
        const int cb = nwarp * 32 + (lane & 3) * 2;
        #pragma unroll
        for (int mf = 0; mf < 2; mf++)
            #pragma unroll
            for (int nf = 0; nf < 4; nf++) {
                int cl = cb + nf * 8;
                float hn0 = Hsf[cl], hn1 = Hsf[cl + 1];
                int j0 = t * 64 + cl;
                float s0 = accH[mf][nf][0] + accC[mf][nf][0] * LO_INV - hn0;
                float s1 = accH[mf][nf][1] + accC[mf][nf][1] * LO_INV - hn1;
                float s2 = accH[mf][nf][2] + accC[mf][nf][2] * LO_INV - hn0;
                float s3 = accH[mf][nf][3] + accC[mf][nf][3] * LO_INV - hn1;
                int r0 = mf * 2, r1 = mf * 2 + 1;
                if (s0 > best[r0]) { best[r0] = s0; bidx[r0] = j0; }
                if (s1 > best[r0]) { best[r0] = s1; bidx[r0] = j0 + 1; }
                if (s2 > best[r1]) { best[r1] = s2; bidx[r1] = j0; }
                if (s3 > best[r1]) { best[r1] = s3; bidx[r1] = j0 + 1; }
            }

        GROUP_BAR(gid);
        if (t + 4 < te) issue_tile(sb, slot, t + 4, ltid);
        CP_COMMIT();
        CP_WAIT1();
        GROUP_BAR(gid);
    }

    #pragma unroll
    for (int rs = 0; rs < 4; rs++) {
        int mf = rs >> 1, rh = rs & 1;
        int row = rt * 128 + mwarp * 32 + mf * 16 + (lane >> 2) + rh * 8;
        atomicMax(&g_best2[row], pack_cand(best[rs], bidx[rs]));
    }
}

// ---------------- tail kernels -----------------------------------------------
__global__ void scatter_kernel(const float* __restrict__ X, int N) {
    int w    = (blockIdx.x * blockDim.x + threadIdx.x) >> 5;
    int lane = threadIdx.x & 31;
    if (w >= N) return;
    int p = g_upos[w];
    int j = (p < 0) ? g_bestidx[w]
                    : (int)(~(unsigned int)(g_best2[p] & 0xffffffffull));
    if (lane == 0) g_bestidx[w] = j;
    float4 v = ((const float4*)(X + (size_t)w * D))[lane];
    float* dst = &g_sums[(size_t)j * D + lane * 4];
    atomicAdd(dst + 0, v.x); atomicAdd(dst + 1, v.y);
    atomicAdd(dst + 2, v.z); atomicAdd(dst + 3, v.w);
    if (lane == 0) atomicAdd(&g_counts[j], 1.0f);
}
__global__ void size_kernel(const float* __restrict__ csize, int K) {
    int j = blockIdx.x * blockDim.x + threadIdx.x;
    float ns = 0.0f;
    if (j < K) {
        ns = csize[j] * 0.99f + g_counts[j] * 0.01f;
        g_counts[j] = ns;
    }
    float tot = blockReduceSum(ns);
    if (threadIdx.x == 0) atomicAdd(&g_scalars[0], tot);
}
__global__ void mean_kernel(const float* __restrict__ csum, int K) {
    int e = blockIdx.x * blockDim.x + threadIdx.x;
    if (e >= K * D) return;
    int j = e >> 7;
    float nsamp = g_scalars[0];
    float smoothed = (g_counts[j] + 1e-5f) * nsamp / (nsamp + (float)K * 1e-5f);
    g_newmean[e] = (csum[e] * 0.99f + g_sums[e] * 0.01f) / smoothed;
}
__global__ void gather_kernel(const float* __restrict__ X, float* __restrict__ out,
                              int N) {
    int e = blockIdx.x * blockDim.x + threadIdx.x;
    int i = e >> 7, d = e & 127;
    int j = g_bestidx[i];
    float q = g_newmean[(size_t)j * D + d];
    float x = X[e];
    out[e] = x + (q - x);
    float df = x - q;
    float tot = blockReduceSum(df * df);
    if (threadIdx.x == 0) atomicAdd(&g_scalars[1], tot);
}
__global__ void final_kernel(float* __restrict__ out, int N, long long out_size) {
    int i = blockIdx.x * blockDim.x + threadIdx.x;
    long long base = (long long)N * D;
    if (i < N && base + i < out_size) out[base + i] = (float)g_bestidx[i];
    if (i == 0 && base + N < out_size)
        out[base + N] = 0.25f * g_scalars[1] / (float)((long long)N * D);
}

// ---------------- launch ------------------------------------------------------
extern "C" void kernel_launch(void* const* d_in, const int* in_sizes, int n_in,
                              void* d_out, int out_size) {
    const float* X     = (const float*)d_in[0];
    const float* E     = (const float*)d_in[1];
    const float* csize = (const float*)d_in[2];
    const float* csum  = (const float*)d_in[3];
    float* out = (float*)d_out;

    int K = in_sizes[2];
    int N = in_sizes[0] / D;

    cudaFuncSetAttribute(argmin_approx, cudaFuncAttributeMaxDynamicSharedMemorySize,
                         S1_SMEM);
    cudaFuncSetAttribute(argmin_exact, cudaFuncAttributeMaxDynamicSharedMemorySize,
                         SMEM_SZ);

    zero_kernel<<<(KPAD * D + 255) / 256, 256>>>();
    halfnorm_kernel<<<(KPAD * 32 + 255) / 256, 256>>>(E, K);
    norms_x<<<(NMAX * 32 + 255) / 256, 256>>>(X);
    prep_a<<<((NMAX / 16) * 256 + 255) / 256, 256>>>(X);
    prep_b<<<((KPAD / 8) * 256 + 255) / 256, 256>>>(E, K);
    argmin_approx<<<(N / 256) * NSEG1, 512, S1_SMEM>>>();
    reduce_rows<<<(N * 32 + 255) / 256, 256>>>();
    prep_a2<<<NMAX / 16, 256>>>(X);
    argmin_exact<<<(N / 128) * NSEG2, 512, SMEM_SZ>>>();
    scatter_kernel<<<(N * 32 + 255) / 256, 256>>>(X, N);
    size_kernel<<<(K + 255) / 256, 256>>>(csize, K);
    mean_kernel<<<(K * D + 255) / 256, 256>>>(csum, K);
    gather_kernel<<<(N * D) / 256, 256>>>(X, out, N);
    final_kernel<<<(N + 255) / 256, 256>>>(out, N, (long long)out_size);
}

// round 8
// speedup vs baseline: 1.1101x; 1.1101x over previous
#include <cuda_runtime.h>
#include <cuda_fp16.h>
#include <cstdint>
#include <math.h>

#define D       128
#define NMAX    32768
#define KPAD    10112                 // 158 tiles * 64
#define NTILE   (KPAD / 64)           // 158
#define NSEG1   4
#define NSEG2   4
#define LO_SCALE   4096.0f
#define LO_INV     (1.0f / 4096.0f)

// ---------------- scratch ----------------------------------------------------
__device__ float g_halfnorm[KPAD];
__device__ int   g_bestidx[NMAX];
__device__ unsigned long long g_best2[NMAX];
__device__ float g_counts[KPAD];
__device__ float g_sums[KPAD * D];
__device__ float g_newmean[KPAD * D];
__device__ float g_scalars[2];
__device__ float g_xh2[NMAX], g_xl2[NMAX];
__device__ int   g_maxE2, g_maxEl2;
__device__ int   g_ucount;
__device__ int   g_ulist[NMAX];
__device__ int   g_upos[NMAX];

// fragment-ordered fp16 operands
__device__ __align__(16) uint4 g_ah4[(NMAX / 16) * 8 * 32];   // A hi
__device__ __align__(16) uint4 g_al4[(NMAX / 16) * 8 * 32];   // A lo
__device__ __align__(16) uint4 g_bf4[(KPAD / 8) * 8 * 32];    // B full {h0,h1,l0,l1}
__device__ __align__(16) uint4 g_bs1[NTILE * 8 * 32 * 4];     // B hi-only (stage1)
__device__ __align__(16) uint4 g_a2h[(NMAX / 16) * 8 * 32];   // stage-2 compact A
__device__ __align__(16) uint4 g_a2l[(NMAX / 16) * 8 * 32];
__device__ __align__(16) uint4 g_chains[NMAX * 64];           // {s1,j1,s2,j2}

// ---------------- helpers ----------------------------------------------------
__device__ __forceinline__ uint32_t smem_to_u32(const void* p) {
    uint32_t a;
    asm("{ .reg .u64 t; cvta.to.shared.u64 t, %1; cvt.u32.u64 %0, t; }"
        : "=r"(a) : "l"(p));
    return a;
}
__device__ __forceinline__ unsigned long long cvta_g(const void* p) {
    unsigned long long r;
    asm("cvta.to.global.u64 %0, %1;" : "=l"(r) : "l"(p));
    return r;
}
__device__ __forceinline__ void cp_async16(uint32_t dst, const void* src) {
    asm volatile("cp.async.cg.shared.global [%0], [%1], 16;"
                 :: "r"(dst), "l"(cvta_g(src)) : "memory");
}
#define CP_COMMIT() asm volatile("cp.async.commit_group;" ::: "memory")
#define CP_WAIT1()  asm volatile("cp.async.wait_group 1;" ::: "memory")
#define GROUP_BAR(g) asm volatile("bar.sync %0, 256;" :: "r"((g) + 1) : "memory")

#define MMA16(d, a, b0, b1) \
    asm volatile("mma.sync.aligned.m16n8k16.row.col.f32.f16.f16.f32 " \
        "{%0,%1,%2,%3},{%4,%5,%6,%7},{%8,%9},{%0,%1,%2,%3};" \
        : "+f"((d)[0]), "+f"((d)[1]), "+f"((d)[2]), "+f"((d)[3]) \
        : "r"((a).x), "r"((a).y), "r"((a).z), "r"((a).w), \
          "r"(b0), "r"(b1))

__device__ __forceinline__ unsigned long long pack_cand(float s, int j) {
    uint32_t u = __float_as_uint(s);
    u = (u & 0x80000000u) ? ~u : (u | 0x80000000u);
    return ((unsigned long long)u << 32) | (uint32_t)(~j);
}
__device__ __forceinline__ uint32_t h2pack(float a, float b) {
    __half2 h = __halves2half2(__float2half_rn(a), __float2half_rn(b));
    return *reinterpret_cast<uint32_t*>(&h);
}
__device__ __forceinline__ float hi_of(float x) {
    return __half2float(__float2half_rn(x));
}
__device__ __forceinline__ float blockReduceSum(float v) {
    __shared__ float sh[32];
    int lane = threadIdx.x & 31, wid = threadIdx.x >> 5;
    #pragma unroll
    for (int o = 16; o > 0; o >>= 1) v += __shfl_down_sync(0xffffffffu, v, o);
    if (lane == 0) sh[wid] = v;
    __syncthreads();
    int nw = (blockDim.x + 31) >> 5;
    v = (wid == 0 && lane < nw) ? sh[lane] : 0.0f;
    if (wid == 0) {
        #pragma unroll
        for (int o = 16; o > 0; o >>= 1) v += __shfl_down_sync(0xffffffffu, v, o);
    }
    return v;
}
__device__ __forceinline__ bool better(float sa, int ja, float sb, int jb) {
    return (sa > sb) || (sa == sb && ja < jb);
}

// ---------------- prep kernels -----------------------------------------------
__global__ void zero_kernel() {
    int i = blockIdx.x * blockDim.x + threadIdx.x;
    if (i < KPAD) g_counts[i] = 0.0f;
    if (i < 2)    g_scalars[i] = 0.0f;
    if (i < NMAX) g_best2[i] = 0ull;
    if (i == 0) { g_ucount = 0; g_maxE2 = 0; g_maxEl2 = 0; }
    int stride = gridDim.x * blockDim.x;
    for (int e = i; e < KPAD * D; e += stride) g_sums[e] = 0.0f;
}
__global__ void halfnorm_kernel(const float* __restrict__ E, int K) {
    int w    = (blockIdx.x * blockDim.x + threadIdx.x) >> 5;
    int lane = threadIdx.x & 31;
    if (w >= KPAD) return;
    if (w >= K) { if (lane == 0) g_halfnorm[w] = INFINITY; return; }
    const float4* row = (const float4*)(E + (size_t)w * D);
    float4 v = row[lane];
    float s = v.x * v.x + v.y * v.y + v.z * v.z + v.w * v.w;
    float hx = hi_of(v.x), hy = hi_of(v.y), hz = hi_of(v.z), hw = hi_of(v.w);
    float lx = v.x - hx, ly = v.y - hy, lz = v.z - hz, lw = v.w - hw;
    float sl = lx * lx + ly * ly + lz * lz + lw * lw;
    #pragma unroll
    for (int o = 16; o > 0; o >>= 1) {
        s  += __shfl_down_sync(0xffffffffu, s, o);
        sl += __shfl_down_sync(0xffffffffu, sl, o);
    }
    if (lane == 0) {
        g_halfnorm[w] = 0.5f * s;
        atomicMax(&g_maxE2,  __float_as_int(s));
        atomicMax(&g_maxEl2, __float_as_int(sl));
    }
}
__global__ void norms_x(const float* __restrict__ X) {
    int w    = (blockIdx.x * blockDim.x + threadIdx.x) >> 5;
    int lane = threadIdx.x & 31;
    if (w >= NMAX) return;
    float4 v = ((const float4*)(X + (size_t)w * D))[lane];
    float hx = hi_of(v.x), hy = hi_of(v.y), hz = hi_of(v.z), hw = hi_of(v.w);
    float lx = v.x - hx, ly = v.y - hy, lz = v.z - hz, lw = v.w - hw;
    float sh2 = hx * hx + hy * hy + hz * hz + hw * hw;
    float sl2 = lx * lx + ly * ly + lz * lz + lw * lw;
    #pragma unroll
    for (int o = 16; o > 0; o >>= 1) {
        sh2 += __shfl_down_sync(0xffffffffu, sh2, o);
        sl2 += __shfl_down_sync(0xffffffffu, sl2, o);
    }
    if (lane == 0) { g_xh2[w] = sqrtf(sh2); g_xl2[w] = sqrtf(sl2); }
}
__global__ void prep_a(const float* __restrict__ X) {
    int t = blockIdx.x * blockDim.x + threadIdx.x;
    if (t >= (NMAX / 16) * 256) return;
    int lane = t & 31, kc = (t >> 5) & 7, mg = t >> 8;
    int r0 = mg * 16 + (lane >> 2);
    int c0 = kc * 16 + (lane & 3) * 2;
    const float* p0 = X + (size_t)r0 * D + c0;
    const float* p1 = X + (size_t)(r0 + 8) * D + c0;
    float x00 = p0[0], x01 = p0[1], x02 = p0[8], x03 = p0[9];
    float x10 = p1[0], x11 = p1[1], x12 = p1[8], x13 = p1[9];
    float h00 = hi_of(x00), h01 = hi_of(x01), h02 = hi_of(x02), h03 = hi_of(x03);
    float h10 = hi_of(x10), h11 = hi_of(x11), h12 = hi_of(x12), h13 = hi_of(x13);
    uint4 hi, lo;
    hi.x = h2pack(h00, h01); hi.y = h2pack(h10, h11);
    hi.z = h2pack(h02, h03); hi.w = h2pack(h12, h13);
    lo.x = h2pack((x00 - h00) * LO_SCALE, (x01 - h01) * LO_SCALE);
    lo.y = h2pack((x10 - h10) * LO_SCALE, (x11 - h11) * LO_SCALE);
    lo.z = h2pack((x02 - h02) * LO_SCALE, (x03 - h03) * LO_SCALE);
    lo.w = h2pack((x12 - h12) * LO_SCALE, (x13 - h13) * LO_SCALE);
    g_ah4[t] = hi;
    g_al4[t] = lo;
}
__global__ void prep_b(const float* __restrict__ E, int K) {
    int t = blockIdx.x * blockDim.x + threadIdx.x;
    if (t >= (KPAD / 8) * 256) return;
    int lane = t & 31, kc = (t >> 5) & 7, ng = t >> 8;
    int j = ng * 8 + (lane >> 2);
    int k0 = kc * 16 + (lane & 3) * 2;
    float b0 = 0.f, b1 = 0.f, b2 = 0.f, b3 = 0.f;
    if (j < K) {
        const float* p = E + (size_t)j * D + k0;
        b0 = p[0]; b1 = p[1]; b2 = p[8]; b3 = p[9];
    }
    float g0 = hi_of(b0), g1 = hi_of(b1), g2 = hi_of(b2), g3 = hi_of(b3);
    uint4 v;
    v.x = h2pack(g0, g1);
    v.y = h2pack(g2, g3);
    v.z = h2pack((b0 - g0) * LO_SCALE, (b1 - g1) * LO_SCALE);
    v.w = h2pack((b2 - g2) * LO_SCALE, (b3 - g3) * LO_SCALE);
    g_bf4[t] = v;
    // stage1 hi-only layout: uint2 at ((tile*8+kc)*32+lane)*8 + nfq
    int tile = ng >> 3, nfq = ng & 7;
    ((uint2*)g_bs1)[(size_t)(((tile * 8 + kc) * 32 + lane) * 8 + nfq)] =
        make_uint2(v.x, v.y);
}

// ---------------- stage 1: hi-only screen, top-2 chains ----------------------
// 512 thr = 2 groups x 8 warps (4m x 2n); warp tile 32x32; M=128/CTA.
#define S1_OFF_B   32768
#define S1_OFF_HS  (S1_OFF_B + 4 * 16384)
#define S1_SMEM    (S1_OFF_HS + 4 * 256)

__device__ __forceinline__ void issue_tile_s1(uint32_t sb, int slot, int t, int ltid) {
    const uint4* src = g_bs1 + (size_t)t * 1024;
    uint32_t dB = sb + S1_OFF_B + slot * 16384;
    #pragma unroll
    for (int i = 0; i < 4; i++) {
        int idx = ltid + i * 256;
        cp_async16(dB + idx * 16, src + idx);
    }
    if (ltid < 16)
        cp_async16(sb + S1_OFF_HS + slot * 256 + ltid * 16,
                   g_halfnorm + t * 64 + ltid * 4);
}

__global__ __launch_bounds__(512, 1)
void argmin_approx() {
    extern __shared__ char smem[];
    uint32_t sb = smem_to_u32(smem);
    const int tid   = threadIdx.x;
    const int gid   = tid >> 8;
    const int ltid  = tid & 255;
    const int lane  = tid & 31;
    const int lwid  = (tid >> 5) & 7;
    const int mwarp = lwid >> 1, nwarp = lwid & 1;
    const int rt  = blockIdx.x >> 2;
    const int seg = blockIdx.x & 3;
    const int tb = (seg * NTILE) / NSEG1;
    const int te = ((seg + 1) * NTILE) / NSEG1;
    const int t0 = tb + gid;
    const int rowbase = rt * 128;

    // prologue: A hi (32KB) + each group's first two B tiles
    {
        const uint4* srcA = g_ah4 + (size_t)rt * 2048;
        #pragma unroll
        for (int i = 0; i < 4; i++) {
            int idx = tid + i * 512;
            cp_async16(sb + idx * 16, srcA + idx);
        }
        if (t0 < te) issue_tile_s1(sb, gid * 2, t0, ltid);
        CP_COMMIT();
        if (t0 + 2 < te) issue_tile_s1(sb, gid * 2 + 1, t0 + 2, ltid);
        CP_COMMIT();
        CP_WAIT1();
        __syncthreads();
    }

    const uint4* As = (const uint4*)smem;

    float b1v[4], b2v[4]; int j1v[4], j2v[4];
    #pragma unroll
    for (int q = 0; q < 4; q++) { b1v[q] = -INFINITY; b2v[q] = -INFINITY; j1v[q] = 0; j2v[q] = 0; }

    int s = 0;
    for (int t = t0; t < te; t += 2, s ^= 1) {
        const int slot = gid * 2 + s;
        const uint4* Bs = (const uint4*)(smem + S1_OFF_B + slot * 16384);

        float acc[2][4][4];
        #pragma unroll
        for (int mf = 0; mf < 2; mf++)
            #pragma unroll
            for (int nf = 0; nf < 4; nf++)
                #pragma unroll
                for (int e = 0; e < 4; e++) acc[mf][nf][e] = 0.0f;

        #pragma unroll
        for (int kc = 0; kc < 8; kc++) {
            uint4 a[2];
            #pragma unroll
            for (int mf = 0; mf < 2; mf++)
                a[mf] = As[((mwarp * 2 + mf) * 8 + kc) * 32 + lane];
            uint4 bq[2];
            #pragma unroll
            for (int q = 0; q < 2; q++)
                bq[q] = Bs[(kc * 32 + lane) * 4 + nwarp * 2 + q];
            #pragma unroll
            for (int q = 0; q < 2; q++)
                #pragma unroll
                for (int mf = 0; mf < 2; mf++) {
                    MMA16(acc[mf][2 * q],     a[mf], bq[q].x, bq[q].y);
                    MMA16(acc[mf][2 * q + 1], a[mf], bq[q].z, bq[q].w);
                }
        }

        // epilogue: top-2 per chain
        const float* Hsf = (const float*)(smem + S1_OFF_HS + slot * 256);
        const int cb = nwarp * 32 + (lane & 3) * 2;
        #pragma unroll
        for (int nf = 0; nf < 4; nf++) {
            int cl = cb + nf * 8;
            float hn0 = Hsf[cl], hn1 = Hsf[cl + 1];
            int j0 = t * 64 + cl;
            #pragma unroll
            for (int mf = 0; mf < 2; mf++) {
                #pragma unroll
                for (int rh = 0; rh < 2; rh++) {
                    int q = mf * 2 + rh;
                    float s0 = acc[mf][nf][rh * 2]     - hn0;
                    float s1 = acc[mf][nf][rh * 2 + 1] - hn1;
                    if (s0 > b1v[q]) { b2v[q] = b1v[q]; j2v[q] = j1v[q]; b1v[q] = s0; j1v[q] = j0; }
                    else if (s0 > b2v[q]) { b2v[q] = s0; j2v[q] = j0; }
                    if (s1 > b1v[q]) { b2v[q] = b1v[q]; j2v[q] = j1v[q]; b1v[q] = s1; j1v[q] = j0 + 1; }
                    else if (s1 > b2v[q]) { b2v[q] = s1; j2v[q] = j0 + 1; }
                }
            }
        }

        GROUP_BAR(gid);
        if (t + 4 < te) issue_tile_s1(sb, slot, t + 4, ltid);
        CP_COMMIT();
        CP_WAIT1();
        GROUP_BAR(gid);
    }

    // write chains: chain = seg*16 + gid*8 + nwarp*4 + (lane&3)
    int chain = seg * 16 + gid * 8 + nwarp * 4 + (lane & 3);
    #pragma unroll
    for (int q = 0; q < 4; q++) {
        int mf = q >> 1, rh = q & 1;
        int row = rowbase + mwarp * 32 + mf * 16 + rh * 8 + (lane >> 2);
        g_chains[(size_t)row * 64 + chain] =
            make_uint4(__float_as_uint(b1v[q]), (uint32_t)j1v[q],
                       __float_as_uint(b2v[q]), (uint32_t)j2v[q]);
    }
}

// ---------------- reduce: exact top-2 per row, margin test -------------------
__device__ __forceinline__ void merge2(float& a1, int& i1, float& a2, int& i2,
                                       float c1, int k1, float c2, int k2) {
    if (better(c1, k1, a1, i1)) {
        float n2; int m2;
        if (better(a1, i1, c2, k2)) { n2 = a1; m2 = i1; } else { n2 = c2; m2 = k2; }
        a1 = c1; i1 = k1; a2 = n2; i2 = m2;
    } else if (better(c1, k1, a2, i2)) {
        a2 = c1; i2 = k1;
    }
}
__global__ void reduce_rows() {
    int w    = (blockIdx.x * blockDim.x + threadIdx.x) >> 5;
    int lane = threadIdx.x & 31;
    if (w >= NMAX) return;
    const uint4* ch = g_chains + (size_t)w * 64;
    uint4 e0 = ch[lane], e1 = ch[lane + 32];
    float a1 = __uint_as_float(e0.x), a2 = __uint_as_float(e0.z);
    int   i1 = (int)e0.y,             i2 = (int)e0.w;
    merge2(a1, i1, a2, i2, __uint_as_float(e1.x), (int)e1.y,
                           __uint_as_float(e1.z), (int)e1.w);
    #pragma unroll
    for (int o = 16; o > 0; o >>= 1) {
        float c1 = __shfl_xor_sync(0xffffffffu, a1, o);
        int   k1 = __shfl_xor_sync(0xffffffffu, i1, o);
        float c2 = __shfl_xor_sync(0xffffffffu, a2, o);
        int   k2 = __shfl_xor_sync(0xffffffffu, i2, o);
        merge2(a1, i1, a2, i2, c1, k1, c2, k2);
    }
    if (lane == 0) {
        float Me  = sqrtf(__int_as_float(g_maxE2));
        float Mel = sqrtf(__int_as_float(g_maxEl2));
        float margin = 1.02f * (g_xl2[w] * Me + g_xh2[w] * Mel)
                     + 2e-5f * g_xh2[w] * Me + 1e-3f;
        g_bestidx[w] = i1;
        if (a2 >= a1 - 2.0f * margin) {
            int pos = atomicAdd(&g_ucount, 1);
            g_ulist[pos] = w;
            g_upos[w] = pos;
        } else {
            g_upos[w] = -1;
        }
    }
}

// ---------------- stage 2 prep: gather uncertain-row fragments ---------------
__global__ void prep_a2(const float* __restrict__ X) {
    int b = blockIdx.x;
    int u = g_ucount;
    int up = (u + 127) & ~127;
    if (b * 16 >= up) return;
    int tid = threadIdx.x;
    int lane = tid & 31, kc = (tid >> 5) & 7;
    int t = b * 256 + tid;
    int i0 = b * 16 + (lane >> 2);
    int i1 = i0 + 8;
    int r0 = (i0 < u) ? g_ulist[i0] : 0;
    int r1 = (i1 < u) ? g_ulist[i1] : 0;
    int c0 = kc * 16 + (lane & 3) * 2;
    const float* p0 = X + (size_t)r0 * D + c0;
    const float* p1 = X + (size_t)r1 * D + c0;
    float x00 = p0[0], x01 = p0[1], x02 = p0[8], x03 = p0[9];
    float x10 = p1[0], x11 = p1[1], x12 = p1[8], x13 = p1[9];
    float h00 = hi_of(x00), h01 = hi_of(x01), h02 = hi_of(x02), h03 = hi_of(x03);
    float h10 = hi_of(x10), h11 = hi_of(x11), h12 = hi_of(x12), h13 = hi_of(x13);
    uint4 hi, lo;
    hi.x = h2pack(h00, h01); hi.y = h2pack(h10, h11);
    hi.z = h2pack(h02, h03); hi.w = h2pack(h12, h13);
    lo.x = h2pack((x00 - h00) * LO_SCALE, (x01 - h01) * LO_SCALE);
    lo.y = h2pack((x10 - h10) * LO_SCALE, (x11 - h11) * LO_SCALE);
    lo.z = h2pack((x02 - h02) * LO_SCALE, (x03 - h03) * LO_SCALE);
    lo.w = h2pack((x12 - h12) * LO_SCALE, (x13 - h13) * LO_SCALE);
    g_a2h[t] = hi;
    g_a2l[t] = lo;
}

// ---------------- stage 2: exact (3-MMA) argmin on compacted rows ------------
#define OFF_AL  32768
#define OFF_B   65536
#define OFF_HS  196608
#define SMEM_SZ 197632

__device__ __forceinline__ void issue_tile(uint32_t sb, int slot, int t, int ltid) {
    const uint4* src = g_bf4 + (size_t)t * 2048;
    uint32_t dB = sb + OFF_B + slot * 32768;
    #pragma unroll
    for (int i = 0; i < 8; i++) {
        int idx = ltid + i * 256;
        cp_async16(dB + idx * 16, src + idx);
    }
    if (ltid < 16)
        cp_async16(sb + OFF_HS + slot * 256 + ltid * 16,
                   g_halfnorm + t * 64 + ltid * 4);
}

__global__ __launch_bounds__(512, 1)
void argmin_exact() {
    int u = g_ucount;
    int up = (u + 127) & ~127;
    const int rt  = blockIdx.x >> 2;
    if (rt * 128 >= up) return;
    extern __shared__ char smem[];
    uint32_t sb = smem_to_u32(smem);
    const int tid   = threadIdx.x;
    const int gid   = tid >> 8;
    const int ltid  = tid & 255;
    const int lane  = tid & 31;
    const int lwid  = (tid >> 5) & 7;
    const int mwarp = lwid >> 1, nwarp = lwid & 1;
    const int seg = blockIdx.x & 3;
    const int tb = (seg * NTILE) / NSEG2;
    const int te = ((seg + 1) * NTILE) / NSEG2;
    const int t0 = tb + gid;

    {
        const uint4* srcH = g_a2h + (size_t)rt * 2048;
        const uint4* srcL = g_a2l + (size_t)rt * 2048;
        #pragma unroll
        for (int i = 0; i < 4; i++) {
            int idx = tid + i * 512;
            cp_async16(sb + idx * 16, srcH + idx);
            cp_async16(sb + OFF_AL + idx * 16, srcL + idx);
        }
        if (t0 < te) issue_tile(sb, gid * 2, t0, ltid);
        CP_COMMIT();
        if (t0 + 2 < te) issue_tile(sb, gid * 2 + 1, t0 + 2, ltid);
        CP_COMMIT();
        CP_WAIT1();
        __syncthreads();
    }

    const uint4* AsH = (const uint4*)smem;
    const uint4* AsL = (const uint4*)(smem + OFF_AL);

    float best[4]; int bidx[4];
    #pragma unroll
    for (int r = 0; r < 4; r++) { best[r] = -INFINITY; bidx[r] = 0; }

    int s = 0;
    for (int t = t0; t < te; t += 2, s ^= 1) {
        const int slot = gid * 2 + s;
        const uint4* Bs = (const uint4*)(smem + OFF_B + slot * 32768);

        float accH[2][4][4], accC[2][4][4];
        #pragma unroll
        for (int mf = 0; mf < 2; mf++)
            #pragma unroll
            for (int nf = 0; nf < 4; nf++)
                #pragma unroll
                for (int e = 0; e < 4; e++) { accH[mf][nf][e] = 0.0f; accC[mf][nf][e] = 0.0f; }

        #pragma unroll
        for (int kc = 0; kc < 8; kc++) {
            uint4 ah[2], al[2];
            #pragma unroll
            for (int mf = 0; mf < 2; mf++) {
                int idx = ((mwarp * 2 + mf) * 8 + kc) * 32 + lane;
                ah[mf] = AsH[idx];
                al[mf] = AsL[idx];
            }
            uint4 bv[4];
            #pragma unroll
            for (int nf = 0; nf < 4; nf++)
                bv[nf] = Bs[((nwarp * 4 + nf) * 8 + kc) * 32 + lane];
            #pragma unroll
            for (int mf = 0; mf < 2; mf++)
                #pragma unroll
                for (int nf = 0; nf < 4; nf++) {
                    MMA16(accH[mf][nf], ah[mf], bv[nf].x, bv[nf].y);
                    MMA16(accC[mf][nf], ah[mf], bv[nf].z, bv[nf].w);
                    MMA16(accC[mf][nf], al[mf], bv[nf].x, bv[nf].y);
                }
        }

        const float* Hsf = (const float*)(smem + OFF_HS + slot * 256);
        const int cb = nwarp * 32 + (lane & 3) * 2;
        #pragma unroll
        for (int mf = 0; mf < 2; mf++)
            #pragma unroll
            for (int nf = 0; nf < 4; nf++) {
                int cl = cb + nf * 8;
                float hn0 = Hsf[cl], hn1 = Hsf[cl + 1];
                int j0 = t * 64 + cl;
                float s0 = accH[mf][nf][0] + accC[mf][nf][0] * LO_INV - hn0;
                float s1 = accH[mf][nf][1] + accC[mf][nf][1] * LO_INV - hn1;
                float s2 = accH[mf][nf][2] + accC[mf][nf][2] * LO_INV - hn0;
                float s3 = accH[mf][nf][3] + accC[mf][nf][3] * LO_INV - hn1;
                int r0 = mf * 2, r1 = mf * 2 + 1;
                if (s0 > best[r0]) { best[r0] = s0; bidx[r0] = j0; }
                if (s1 > best[r0]) { best[r0] = s1; bidx[r0] = j0 + 1; }
                if (s2 > best[r1]) { best[r1] = s2; bidx[r1] = j0; }
                if (s3 > best[r1]) { best[r1] = s3; bidx[r1] = j0 + 1; }
            }

        GROUP_BAR(gid);
        if (t + 4 < te) issue_tile(sb, slot, t + 4, ltid);
        CP_COMMIT();
        CP_WAIT1();
        GROUP_BAR(gid);
    }

    #pragma unroll
    for (int rs = 0; rs < 4; rs++) {
        int mf = rs >> 1, rh = rs & 1;
        int row = rt * 128 + mwarp * 32 + mf * 16 + (lane >> 2) + rh * 8;
        atomicMax(&g_best2[row], pack_cand(best[rs], bidx[rs]));
    }
}

// ---------------- tail kernels -----------------------------------------------
__global__ void scatter_kernel(const float* __restrict__ X, int N) {
    int w    = (blockIdx.x * blockDim.x + threadIdx.x) >> 5;
    int lane = threadIdx.x & 31;
    if (w >= N) return;
    int p = g_upos[w];
    int j = (p < 0) ? g_bestidx[w]
                    : (int)(~(unsigned int)(g_best2[p] & 0xffffffffull));
    if (lane == 0) g_bestidx[w] = j;
    float4 v = ((const float4*)(X + (size_t)w * D))[lane];
    float* dst = &g_sums[(size_t)j * D + lane * 4];
    atomicAdd(dst + 0, v.x); atomicAdd(dst + 1, v.y);
    atomicAdd(dst + 2, v.z); atomicAdd(dst + 3, v.w);
    if (lane == 0) atomicAdd(&g_counts[j], 1.0f);
}
__global__ void size_kernel(const float* __restrict__ csize, int K) {
    int j = blockIdx.x * blockDim.x + threadIdx.x;
    float ns = 0.0f;
    if (j < K) {
        ns = csize[j] * 0.99f + g_counts[j] * 0.01f;
        g_counts[j] = ns;
    }
    float tot = blockReduceSum(ns);
    if (threadIdx.x == 0) atomicAdd(&g_scalars[0], tot);
}
__global__ void mean_kernel(const float* __restrict__ csum, int K) {
    int e = blockIdx.x * blockDim.x + threadIdx.x;
    if (e >= K * D) return;
    int j = e >> 7;
    float nsamp = g_scalars[0];
    float smoothed = (g_counts[j] + 1e-5f) * nsamp / (nsamp + (float)K * 1e-5f);
    g_newmean[e] = (csum[e] * 0.99f + g_sums[e] * 0.01f) / smoothed;
}
__global__ void gather_kernel(const float* __restrict__ X, float* __restrict__ out,
                              int N) {
    int e = blockIdx.x * blockDim.x + threadIdx.x;
    int i = e >> 7, d = e & 127;
    int j = g_bestidx[i];
    float q = g_newmean[(size_t)j * D + d];
    float x = X[e];
    out[e] = x + (q - x);
    float df = x - q;
    float tot = blockReduceSum(df * df);
    if (threadIdx.x == 0) atomicAdd(&g_scalars[1], tot);
}
__global__ void final_kernel(float* __restrict__ out, int N, long long out_size) {
    int i = blockIdx.x * blockDim.x + threadIdx.x;
    long long base = (long long)N * D;
    if (i < N && base + i < out_size) out[base + i] = (float)g_bestidx[i];
    if (i == 0 && base + N < out_size)
        out[base + N] = 0.25f * g_scalars[1] / (float)((long long)N * D);
}

// ---------------- launch ------------------------------------------------------
extern "C" void kernel_launch(void* const* d_in, const int* in_sizes, int n_in,
                              void* d_out, int out_size) {
    const float* X     = (const float*)d_in[0];
    const float* E     = (const float*)d_in[1];
    const float* csize = (const float*)d_in[2];
    const float* csum  = (const float*)d_in[3];
    float* out = (float*)d_out;

    int K = in_sizes[2];
    int N = in_sizes[0] / D;

    cudaFuncSetAttribute(argmin_approx, cudaFuncAttributeMaxDynamicSharedMemorySize,
                         S1_SMEM);
    cudaFuncSetAttribute(argmin_exact, cudaFuncAttributeMaxDynamicSharedMemorySize,
                         SMEM_SZ);

    zero_kernel<<<(KPAD * D + 255) / 256, 256>>>();
    halfnorm_kernel<<<(KPAD * 32 + 255) / 256, 256>>>(E, K);
    norms_x<<<(NMAX * 32 + 255) / 256, 256>>>(X);
    prep_a<<<((NMAX / 16) * 256 + 255) / 256, 256>>>(X);
    prep_b<<<((KPAD / 8) * 256 + 255) / 256, 256>>>(E, K);
    argmin_approx<<<(N / 128) * NSEG1, 512, S1_SMEM>>>();
    reduce_rows<<<(N * 32 + 255) / 256, 256>>>();
    prep_a2<<<NMAX / 16, 256>>>(X);
    argmin_exact<<<(N / 128) * NSEG2, 512, SMEM_SZ>>>();
    scatter_kernel<<<(N * 32 + 255) / 256, 256>>>(X, N);
    size_kernel<<<(K + 255) / 256, 256>>>(csize, K);
    mean_kernel<<<(K * D + 255) / 256, 256>>>(csum, K);
    gather_kernel<<<(N * D) / 256, 256>>>(X, out, N);
    final_kernel<<<(N + 255) / 256, 256>>>(out, N, (long long)out_size);
}

// round 9
// speedup vs baseline: 1.3786x; 1.2418x over previous
#include <cuda_runtime.h>
#include <cuda_fp16.h>
#include <cstdint>
#include <math.h>

#define D       128
#define NMAX    32768
#define KPAD    10112                 // 158 tiles * 64
#define NTILE   (KPAD / 64)           // 158
#define NSEG1   4
#define NSEG2   8
#define LO_SCALE   4096.0f
#define LO_INV     (1.0f / 4096.0f)

// ---------------- scratch ----------------------------------------------------
__device__ float g_halfnorm[KPAD];
__device__ int   g_bestidx[NMAX];
__device__ unsigned long long g_best2[NMAX];
__device__ float g_counts[KPAD];
__device__ float g_sums[KPAD * D];
__device__ float g_newmean[KPAD * D];
__device__ float g_scalars[2];
__device__ float g_xh2[NMAX], g_xl2[NMAX];
__device__ int   g_maxE2, g_maxEl2;
__device__ int   g_ucount;
__device__ int   g_ulist[NMAX];
__device__ int   g_upos[NMAX];

// fragment-ordered fp16 operands
__device__ __align__(16) uint4 g_ah4[(NMAX / 16) * 8 * 32];   // A hi
__device__ __align__(16) uint4 g_al4[(NMAX / 16) * 8 * 32];   // A lo
__device__ __align__(16) uint4 g_bf4[(KPAD / 8) * 8 * 32];    // B full {h0,h1,l0,l1}
__device__ __align__(16) uint4 g_bs1[NTILE * 8 * 32 * 4];     // B hi-only (stage1)
__device__ __align__(16) uint4 g_a2h[(NMAX / 16) * 8 * 32];   // stage-2 compact A
__device__ __align__(16) uint4 g_a2l[(NMAX / 16) * 8 * 32];
__device__ __align__(16) uint4 g_chains[NMAX * 64];           // {s1,j1,s2,j2}

// ---------------- helpers ----------------------------------------------------
__device__ __forceinline__ uint32_t smem_to_u32(const void* p) {
    uint32_t a;
    asm("{ .reg .u64 t; cvta.to.shared.u64 t, %1; cvt.u32.u64 %0, t; }"
        : "=r"(a) : "l"(p));
    return a;
}
__device__ __forceinline__ unsigned long long cvta_g(const void* p) {
    unsigned long long r;
    asm("cvta.to.global.u64 %0, %1;" : "=l"(r) : "l"(p));
    return r;
}
__device__ __forceinline__ void cp_async16(uint32_t dst, const void* src) {
    asm volatile("cp.async.cg.shared.global [%0], [%1], 16;"
                 :: "r"(dst), "l"(cvta_g(src)) : "memory");
}
#define CP_COMMIT() asm volatile("cp.async.commit_group;" ::: "memory")
#define CP_WAIT1()  asm volatile("cp.async.wait_group 1;" ::: "memory")
#define GROUP_BAR(g) asm volatile("bar.sync %0, 256;" :: "r"((g) + 1) : "memory")

#define MMA16(d, a, b0, b1) \
    asm volatile("mma.sync.aligned.m16n8k16.row.col.f32.f16.f16.f32 " \
        "{%0,%1,%2,%3},{%4,%5,%6,%7},{%8,%9},{%0,%1,%2,%3};" \
        : "+f"((d)[0]), "+f"((d)[1]), "+f"((d)[2]), "+f"((d)[3]) \
        : "r"((a).x), "r"((a).y), "r"((a).z), "r"((a).w), \
          "r"(b0), "r"(b1))

__device__ __forceinline__ unsigned long long pack_cand(float s, int j) {
    uint32_t u = __float_as_uint(s);
    u = (u & 0x80000000u) ? ~u : (u | 0x80000000u);
    return ((unsigned long long)u << 32) | (uint32_t)(~j);
}
__device__ __forceinline__ uint32_t h2pack(float a, float b) {
    __half2 h = __halves2half2(__float2half_rn(a), __float2half_rn(b));
    return *reinterpret_cast<uint32_t*>(&h);
}
__device__ __forceinline__ float hi_of(float x) {
    return __half2float(__float2half_rn(x));
}
__device__ __forceinline__ float blockReduceSum(float v) {
    __shared__ float sh[32];
    int lane = threadIdx.x & 31, wid = threadIdx.x >> 5;
    #pragma unroll
    for (int o = 16; o > 0; o >>= 1) v += __shfl_down_sync(0xffffffffu, v, o);
    if (lane == 0) sh[wid] = v;
    __syncthreads();
    int nw = (blockDim.x + 31) >> 5;
    v = (wid == 0 && lane < nw) ? sh[lane] : 0.0f;
    if (wid == 0) {
        #pragma unroll
        for (int o = 16; o > 0; o >>= 1) v += __shfl_down_sync(0xffffffffu, v, o);
    }
    return v;
}
__device__ __forceinline__ bool better(float sa, int ja, float sb, int jb) {
    return (sa > sb) || (sa == sb && ja < jb);
}

// ---------------- prep kernels -----------------------------------------------
__global__ void zero_kernel() {
    int i = blockIdx.x * blockDim.x + threadIdx.x;
    if (i < KPAD) g_counts[i] = 0.0f;
    if (i < 2)    g_scalars[i] = 0.0f;
    if (i < NMAX) g_best2[i] = 0ull;
    if (i == 0) { g_ucount = 0; g_maxE2 = 0; g_maxEl2 = 0; }
    int stride = gridDim.x * blockDim.x;
    for (int e = i; e < KPAD * D; e += stride) g_sums[e] = 0.0f;
}
__global__ void halfnorm_kernel(const float* __restrict__ E, int K) {
    int w    = (blockIdx.x * blockDim.x + threadIdx.x) >> 5;
    int lane = threadIdx.x & 31;
    if (w >= KPAD) return;
    if (w >= K) { if (lane == 0) g_halfnorm[w] = INFINITY; return; }
    const float4* row = (const float4*)(E + (size_t)w * D);
    float4 v = row[lane];
    float s = v.x * v.x + v.y * v.y + v.z * v.z + v.w * v.w;
    float hx = hi_of(v.x), hy = hi_of(v.y), hz = hi_of(v.z), hw = hi_of(v.w);
    float lx = v.x - hx, ly = v.y - hy, lz = v.z - hz, lw = v.w - hw;
    float sl = lx * lx + ly * ly + lz * lz + lw * lw;
    #pragma unroll
    for (int o = 16; o > 0; o >>= 1) {
        s  += __shfl_down_sync(0xffffffffu, s, o);
        sl += __shfl_down_sync(0xffffffffu, sl, o);
    }
    if (lane == 0) {
        g_halfnorm[w] = 0.5f * s;
        atomicMax(&g_maxE2,  __float_as_int(s));
        atomicMax(&g_maxEl2, __float_as_int(sl));
    }
}
__global__ void norms_x(const float* __restrict__ X) {
    int w    = (blockIdx.x * blockDim.x + threadIdx.x) >> 5;
    int lane = threadIdx.x & 31;
    if (w >= NMAX) return;
    float4 v = ((const float4*)(X + (size_t)w * D))[lane];
    float hx = hi_of(v.x), hy = hi_of(v.y), hz = hi_of(v.z), hw = hi_of(v.w);
    float lx = v.x - hx, ly = v.y - hy, lz = v.z - hz, lw = v.w - hw;
    float sh2 = hx * hx + hy * hy + hz * hz + hw * hw;
    float sl2 = lx * lx + ly * ly + lz * lz + lw * lw;
    #pragma unroll
    for (int o = 16; o > 0; o >>= 1) {
        sh2 += __shfl_down_sync(0xffffffffu, sh2, o);
        sl2 += __shfl_down_sync(0xffffffffu, sl2, o);
    }
    if (lane == 0) { g_xh2[w] = sqrtf(sh2); g_xl2[w] = sqrtf(sl2); }
}
__global__ void prep_a(const float* __restrict__ X) {
    int t = blockIdx.x * blockDim.x + threadIdx.x;
    if (t >= (NMAX / 16) * 256) return;
    int lane = t & 31, kc = (t >> 5) & 7, mg = t >> 8;
    int r0 = mg * 16 + (lane >> 2);
    int c0 = kc * 16 + (lane & 3) * 2;
    const float* p0 = X + (size_t)r0 * D + c0;
    const float* p1 = X + (size_t)(r0 + 8) * D + c0;
    float x00 = p0[0], x01 = p0[1], x02 = p0[8], x03 = p0[9];
    float x10 = p1[0], x11 = p1[1], x12 = p1[8], x13 = p1[9];
    float h00 = hi_of(x00), h01 = hi_of(x01), h02 = hi_of(x02), h03 = hi_of(x03);
    float h10 = hi_of(x10), h11 = hi_of(x11), h12 = hi_of(x12), h13 = hi_of(x13);
    uint4 hi, lo;
    hi.x = h2pack(h00, h01); hi.y = h2pack(h10, h11);
    hi.z = h2pack(h02, h03); hi.w = h2pack(h12, h13);
    lo.x = h2pack((x00 - h00) * LO_SCALE, (x01 - h01) * LO_SCALE);
    lo.y = h2pack((x10 - h10) * LO_SCALE, (x11 - h11) * LO_SCALE);
    lo.z = h2pack((x02 - h02) * LO_SCALE, (x03 - h03) * LO_SCALE);
    lo.w = h2pack((x12 - h12) * LO_SCALE, (x13 - h13) * LO_SCALE);
    g_ah4[t] = hi;
    g_al4[t] = lo;
}
__global__ void prep_b(const float* __restrict__ E, int K) {
    int t = blockIdx.x * blockDim.x + threadIdx.x;
    if (t >= (KPAD / 8) * 256) return;
    int lane = t & 31, kc = (t >> 5) & 7, ng = t >> 8;
    int j = ng * 8 + (lane >> 2);
    int k0 = kc * 16 + (lane & 3) * 2;
    float b0 = 0.f, b1 = 0.f, b2 = 0.f, b3 = 0.f;
    if (j < K) {
        const float* p = E + (size_t)j * D + k0;
        b0 = p[0]; b1 = p[1]; b2 = p[8]; b3 = p[9];
    }
    float g0 = hi_of(b0), g1 = hi_of(b1), g2 = hi_of(b2), g3 = hi_of(b3);
    uint4 v;
    v.x = h2pack(g0, g1);
    v.y = h2pack(g2, g3);
    v.z = h2pack((b0 - g0) * LO_SCALE, (b1 - g1) * LO_SCALE);
    v.w = h2pack((b2 - g2) * LO_SCALE, (b3 - g3) * LO_SCALE);
    g_bf4[t] = v;
    // stage1 hi-only layout (conflict-free: lane is 16B-stride fastest dim):
    // uint4 index = ((tile*8 + kc)*4 + jq)*32 + lane ; halves packed in .xy/.zw
    int tile = ng >> 3, nfq = ng & 7, jq = nfq >> 1, half = nfq & 1;
    ((uint2*)g_bs1)[(size_t)((((tile * 8 + kc) * 4 + jq) * 32 + lane) * 2 + half)] =
        make_uint2(v.x, v.y);
}

// ---------------- stage 1: hi-only screen, top-2 chains ----------------------
// 512 thr = 2 groups x 8 warps (4m x 2n); warp tile 32x32; M=128/CTA.
#define S1_OFF_B   32768
#define S1_OFF_HS  (S1_OFF_B + 4 * 16384)
#define S1_SMEM    (S1_OFF_HS + 4 * 256)

__device__ __forceinline__ void issue_tile_s1(uint32_t sb, int slot, int t, int ltid) {
    const uint4* src = g_bs1 + (size_t)t * 1024;
    uint32_t dB = sb + S1_OFF_B + slot * 16384;
    #pragma unroll
    for (int i = 0; i < 4; i++) {
        int idx = ltid + i * 256;
        cp_async16(dB + idx * 16, src + idx);
    }
    if (ltid < 16)
        cp_async16(sb + S1_OFF_HS + slot * 256 + ltid * 16,
                   g_halfnorm + t * 64 + ltid * 4);
}

__global__ __launch_bounds__(512, 1)
void argmin_approx() {
    extern __shared__ char smem[];
    uint32_t sb = smem_to_u32(smem);
    const int tid   = threadIdx.x;
    const int gid   = tid >> 8;
    const int ltid  = tid & 255;
    const int lane  = tid & 31;
    const int lwid  = (tid >> 5) & 7;
    const int mwarp = lwid >> 1, nwarp = lwid & 1;
    const int rt  = blockIdx.x >> 2;
    const int seg = blockIdx.x & 3;
    const int tb = (seg * NTILE) / NSEG1;
    const int te = ((seg + 1) * NTILE) / NSEG1;
    const int t0 = tb + gid;
    const int rowbase = rt * 128;

    // prologue: A hi (32KB) + each group's first two B tiles
    {
        const uint4* srcA = g_ah4 + (size_t)rt * 2048;
        #pragma unroll
        for (int i = 0; i < 4; i++) {
            int idx = tid + i * 512;
            cp_async16(sb + idx * 16, srcA + idx);
        }
        if (t0 < te) issue_tile_s1(sb, gid * 2, t0, ltid);
        CP_COMMIT();
        if (t0 + 2 < te) issue_tile_s1(sb, gid * 2 + 1, t0 + 2, ltid);
        CP_COMMIT();
        CP_WAIT1();
        __syncthreads();
    }

    const uint4* As = (const uint4*)smem;

    float b1v[4], b2v[4]; int j1v[4], j2v[4];
    #pragma unroll
    for (int q = 0; q < 4; q++) { b1v[q] = -INFINITY; b2v[q] = -INFINITY; j1v[q] = 0; j2v[q] = 0; }

    int s = 0;
    for (int t = t0; t < te; t += 2, s ^= 1) {
        const int slot = gid * 2 + s;
        const uint4* Bs = (const uint4*)(smem + S1_OFF_B + slot * 16384);

        float acc[2][4][4];
        #pragma unroll
        for (int mf = 0; mf < 2; mf++)
            #pragma unroll
            for (int nf = 0; nf < 4; nf++)
                #pragma unroll
                for (int e = 0; e < 4; e++) acc[mf][nf][e] = 0.0f;

        #pragma unroll
        for (int kc = 0; kc < 8; kc++) {
            uint4 a[2];
            #pragma unroll
            for (int mf = 0; mf < 2; mf++)
                a[mf] = As[((mwarp * 2 + mf) * 8 + kc) * 32 + lane];
            uint4 bq[2];
            #pragma unroll
            for (int q = 0; q < 2; q++)
                bq[q] = Bs[(kc * 4 + nwarp * 2 + q) * 32 + lane];
            #pragma unroll
            for (int q = 0; q < 2; q++)
                #pragma unroll
                for (int mf = 0; mf < 2; mf++) {
                    MMA16(acc[mf][2 * q],     a[mf], bq[q].x, bq[q].y);
                    MMA16(acc[mf][2 * q + 1], a[mf], bq[q].z, bq[q].w);
                }
        }

        // epilogue: top-2 per chain
        const float* Hsf = (const float*)(smem + S1_OFF_HS + slot * 256);
        const int cb = nwarp * 32 + (lane & 3) * 2;
        #pragma unroll
        for (int nf = 0; nf < 4; nf++) {
            int cl = cb + nf * 8;
            float hn0 = Hsf[cl], hn1 = Hsf[cl + 1];
            int j0 = t * 64 + cl;
            #pragma unroll
            for (int mf = 0; mf < 2; mf++) {
                #pragma unroll
                for (int rh = 0; rh < 2; rh++) {
                    int q = mf * 2 + rh;
                    float s0 = acc[mf][nf][rh * 2]     - hn0;
                    float s1 = acc[mf][nf][rh * 2 + 1] - hn1;
                    if (s0 > b1v[q]) { b2v[q] = b1v[q]; j2v[q] = j1v[q]; b1v[q] = s0; j1v[q] = j0; }
                    else if (s0 > b2v[q]) { b2v[q] = s0; j2v[q] = j0; }
                    if (s1 > b1v[q]) { b2v[q] = b1v[q]; j2v[q] = j1v[q]; b1v[q] = s1; j1v[q] = j0 + 1; }
                    else if (s1 > b2v[q]) { b2v[q] = s1; j2v[q] = j0 + 1; }
                }
            }
        }

        GROUP_BAR(gid);
        if (t + 4 < te) issue_tile_s1(sb, slot, t + 4, ltid);
        CP_COMMIT();
        CP_WAIT1();
        GROUP_BAR(gid);
    }

    // write chains: chain = seg*16 + gid*8 + nwarp*4 + (lane&3)
    int chain = seg * 16 + gid * 8 + nwarp * 4 + (lane & 3);
    #pragma unroll
    for (int q = 0; q < 4; q++) {
        int mf = q >> 1, rh = q & 1;
        int row = rowbase + mwarp * 32 + mf * 16 + rh * 8 + (lane >> 2);
        g_chains[(size_t)row * 64 + chain] =
            make_uint4(__float_as_uint(b1v[q]), (uint32_t)j1v[q],
                       __float_as_uint(b2v[q]), (uint32_t)j2v[q]);
    }
}

// ---------------- reduce: exact top-2 per row, margin test -------------------
__device__ __forceinline__ void merge2(float& a1, int& i1, float& a2, int& i2,
                                       float c1, int k1, float c2, int k2) {
    if (better(c1, k1, a1, i1)) {
        float n2; int m2;
        if (better(a1, i1, c2, k2)) { n2 = a1; m2 = i1; } else { n2 = c2; m2 = k2; }
        a1 = c1; i1 = k1; a2 = n2; i2 = m2;
    } else if (better(c1, k1, a2, i2)) {
        a2 = c1; i2 = k1;
    }
}
__global__ void reduce_rows() {
    int w    = (blockIdx.x * blockDim.x + threadIdx.x) >> 5;
    int lane = threadIdx.x & 31;
    if (w >= NMAX) return;
    const uint4* ch = g_chains + (size_t)w * 64;
    uint4 e0 = ch[lane], e1 = ch[lane + 32];
    float a1 = __uint_as_float(e0.x), a2 = __uint_as_float(e0.z);
    int   i1 = (int)e0.y,             i2 = (int)e0.w;
    merge2(a1, i1, a2, i2, __uint_as_float(e1.x), (int)e1.y,
                           __uint_as_float(e1.z), (int)e1.w);
    #pragma unroll
    for (int o = 16; o > 0; o >>= 1) {
        float c1 = __shfl_xor_sync(0xffffffffu, a1, o);
        int   k1 = __shfl_xor_sync(0xffffffffu, i1, o);
        float c2 = __shfl_xor_sync(0xffffffffu, a2, o);
        int   k2 = __shfl_xor_sync(0xffffffffu, i2, o);
        merge2(a1, i1, a2, i2, c1, k1, c2, k2);
    }
    if (lane == 0) {
        float Me  = sqrtf(__int_as_float(g_maxE2));
        float Mel = sqrtf(__int_as_float(g_maxEl2));
        float margin = 1.02f * (g_xl2[w] * Me + g_xh2[w] * Mel)
                     + 2e-5f * g_xh2[w] * Me + 1e-3f;
        g_bestidx[w] = i1;
        if (a2 >= a1 - 2.0f * margin) {
            int pos = atomicAdd(&g_ucount, 1);
            g_ulist[pos] = w;
            g_upos[w] = pos;
        } else {
            g_upos[w] = -1;
        }
    }
}

// ---------------- stage 2 prep: gather uncertain-row fragments ---------------
__global__ void prep_a2(const float* __restrict__ X) {
    int b = blockIdx.x;
    int u = g_ucount;
    int up = (u + 127) & ~127;
    if (b * 16 >= up) return;
    int tid = threadIdx.x;
    int lane = tid & 31, kc = (tid >> 5) & 7;
    int t = b * 256 + tid;
    int i0 = b * 16 + (lane >> 2);
    int i1 = i0 + 8;
    int r0 = (i0 < u) ? g_ulist[i0] : 0;
    int r1 = (i1 < u) ? g_ulist[i1] : 0;
    int c0 = kc * 16 + (lane & 3) * 2;
    const float* p0 = X + (size_t)r0 * D + c0;
    const float* p1 = X + (size_t)r1 * D + c0;
    float x00 = p0[0], x01 = p0[1], x02 = p0[8], x03 = p0[9];
    float x10 = p1[0], x11 = p1[1], x12 = p1[8], x13 = p1[9];
    float h00 = hi_of(x00), h01 = hi_of(x01), h02 = hi_of(x02), h03 = hi_of(x03);
    float h10 = hi_of(x10), h11 = hi_of(x11), h12 = hi_of(x12), h13 = hi_of(x13);
    uint4 hi, lo;
    hi.x = h2pack(h00, h01); hi.y = h2pack(h10, h11);
    hi.z = h2pack(h02, h03); hi.w = h2pack(h12, h13);
    lo.x = h2pack((x00 - h00) * LO_SCALE, (x01 - h01) * LO_SCALE);
    lo.y = h2pack((x10 - h10) * LO_SCALE, (x11 - h11) * LO_SCALE);
    lo.z = h2pack((x02 - h02) * LO_SCALE, (x03 - h03) * LO_SCALE);
    lo.w = h2pack((x12 - h12) * LO_SCALE, (x13 - h13) * LO_SCALE);
    g_a2h[t] = hi;
    g_a2l[t] = lo;
}

// ---------------- stage 2: exact (3-MMA) argmin on compacted rows ------------
#define OFF_AL  32768
#define OFF_B   65536
#define OFF_HS  196608
#define SMEM_SZ 197632

__device__ __forceinline__ void issue_tile(uint32_t sb, int slot, int t, int ltid) {
    const uint4* src = g_bf4 + (size_t)t * 2048;
    uint32_t dB = sb + OFF_B + slot * 32768;
    #pragma unroll
    for (int i = 0; i < 8; i++) {
        int idx = ltid + i * 256;
        cp_async16(dB + idx * 16, src + idx);
    }
    if (ltid < 16)
        cp_async16(sb + OFF_HS + slot * 256 + ltid * 16,
                   g_halfnorm + t * 64 + ltid * 4);
}

__global__ __launch_bounds__(512, 1)
void argmin_exact() {
    int u = g_ucount;
    int up = (u + 127) & ~127;
    const int rt  = blockIdx.x >> 3;
    if (rt * 128 >= up) return;
    extern __shared__ char smem[];
    uint32_t sb = smem_to_u32(smem);
    const int tid   = threadIdx.x;
    const int gid   = tid >> 8;
    const int ltid  = tid & 255;
    const int lane  = tid & 31;
    const int lwid  = (tid >> 5) & 7;
    const int mwarp = lwid >> 1, nwarp = lwid & 1;
    const int seg = blockIdx.x & 7;
    const int tb = (seg * NTILE) / NSEG2;
    const int te = ((seg + 1) * NTILE) / NSEG2;
    const int t0 = tb + gid;

    {
        const uint4* srcH = g_a2h + (size_t)rt * 2048;
        const uint4* srcL = g_a2l + (size_t)rt * 2048;
        #pragma unroll
        for (int i = 0; i < 4; i++) {
            int idx = tid + i * 512;
            cp_async16(sb + idx * 16, srcH + idx);
            cp_async16(sb + OFF_AL + idx * 16, srcL + idx);
        }
        if (t0 < te) issue_tile(sb, gid * 2, t0, ltid);
        CP_COMMIT();
        if (t0 + 2 < te) issue_tile(sb, gid * 2 + 1, t0 + 2, ltid);
        CP_COMMIT();
        CP_WAIT1();
        __syncthreads();
    }

    const uint4* AsH = (const uint4*)smem;
    const uint4* AsL = (const uint4*)(smem + OFF_AL);

    float best[4]; int bidx[4];
    #pragma unroll
    for (int r = 0; r < 4; r++) { best[r] = -INFINITY; bidx[r] = 0; }

    int s = 0;
    for (int t = t0; t < te; t += 2, s ^= 1) {
        const int slot = gid * 2 + s;
        const uint4* Bs = (const uint4*)(smem + OFF_B + slot * 32768);

        float accH[2][4][4], accC[2][4][4];
        #pragma unroll
        for (int mf = 0; mf < 2; mf++)
            #pragma unroll
            for (int nf = 0; nf < 4; nf++)
                #pragma unroll
                for (int e = 0; e < 4; e++) { accH[mf][nf][e] = 0.0f; accC[mf][nf][e] = 0.0f; }

        #pragma unroll
        for (int kc = 0; kc < 8; kc++) {
            uint4 ah[2], al[2];
            #pragma unroll
            for (int mf = 0; mf < 2; mf++) {
                int idx = ((mwarp * 2 + mf) * 8 + kc) * 32 + lane;
                ah[mf] = AsH[idx];
                al[mf] = AsL[idx];
            }
            uint4 bv[4];
            #pragma unroll
            for (int nf = 0; nf < 4; nf++)
                bv[nf] = Bs[((nwarp * 4 + nf) * 8 + kc) * 32 + lane];
            #pragma unroll
            for (int mf = 0; mf < 2; mf++)
                #pragma unroll
                for (int nf = 0; nf < 4; nf++) {
                    MMA16(accH[mf][nf], ah[mf], bv[nf].x, bv[nf].y);
                    MMA16(accC[mf][nf], ah[mf], bv[nf].z, bv[nf].w);
                    MMA16(accC[mf][nf], al[mf], bv[nf].x, bv[nf].y);
                }
        }

        const float* Hsf = (const float*)(smem + OFF_HS + slot * 256);
        const int cb = nwarp * 32 + (lane & 3) * 2;
        #pragma unroll
        for (int mf = 0; mf < 2; mf++)
            #pragma unroll
            for (int nf = 0; nf < 4; nf++) {
                int cl = cb + nf * 8;
                float hn0 = Hsf[cl], hn1 = Hsf[cl + 1];
                int j0 = t * 64 + cl;
                float s0 = accH[mf][nf][0] + accC[mf][nf][0] * LO_INV - hn0;
                float s1 = accH[mf][nf][1] + accC[mf][nf][1] * LO_INV - hn1;
                float s2 = accH[mf][nf][2] + accC[mf][nf][2] * LO_INV - hn0;
                float s3 = accH[mf][nf][3] + accC[mf][nf][3] * LO_INV - hn1;
                int r0 = mf * 2, r1 = mf * 2 + 1;
                if (s0 > best[r0]) { best[r0] = s0; bidx[r0] = j0; }
                if (s1 > best[r0]) { best[r0] = s1; bidx[r0] = j0 + 1; }
                if (s2 > best[r1]) { best[r1] = s2; bidx[r1] = j0; }
                if (s3 > best[r1]) { best[r1] = s3; bidx[r1] = j0 + 1; }
            }

        GROUP_BAR(gid);
        if (t + 4 < te) issue_tile(sb, slot, t + 4, ltid);
        CP_COMMIT();
        CP_WAIT1();
        GROUP_BAR(gid);
    }

    #pragma unroll
    for (int rs = 0; rs < 4; rs++) {
        int mf = rs >> 1, rh = rs & 1;
        int row = rt * 128 + mwarp * 32 + mf * 16 + (lane >> 2) + rh * 8;
        atomicMax(&g_best2[row], pack_cand(best[rs], bidx[rs]));
    }
}

// ---------------- tail kernels -----------------------------------------------
__global__ void scatter_kernel(const float* __restrict__ X, int N) {
    int w    = (blockIdx.x * blockDim.x + threadIdx.x) >> 5;
    int lane = threadIdx.x & 31;
    if (w >= N) return;
    int p = g_upos[w];
    int j = (p < 0) ? g_bestidx[w]
                    : (int)(~(unsigned int)(g_best2[p] & 0xffffffffull));
    if (lane == 0) g_bestidx[w] = j;
    float4 v = ((const float4*)(X + (size_t)w * D))[lane];
    float* dst = &g_sums[(size_t)j * D + lane * 4];
    atomicAdd(dst + 0, v.x); atomicAdd(dst + 1, v.y);
    atomicAdd(dst + 2, v.z); atomicAdd(dst + 3, v.w);
    if (lane == 0) atomicAdd(&g_counts[j], 1.0f);
}
__global__ void size_kernel(const float* __restrict__ csize, int K) {
    int j = blockIdx.x * blockDim.x + threadIdx.x;
    float ns = 0.0f;
    if (j < K) {
        ns = csize[j] * 0.99f + g_counts[j] * 0.01f;
        g_counts[j] = ns;
    }
    float tot = blockReduceSum(ns);
    if (threadIdx.x == 0) atomicAdd(&g_scalars[0], tot);
}
__global__ void mean_kernel(const float* __restrict__ csum, int K) {
    int e = blockIdx.x * blockDim.x + threadIdx.x;
    if (e >= K * D) return;
    int j = e >> 7;
    float nsamp = g_scalars[0];
    float smoothed = (g_counts[j] + 1e-5f) * nsamp / (nsamp + (float)K * 1e-5f);
    g_newmean[e] = (csum[e] * 0.99f + g_sums[e] * 0.01f) / smoothed;
}
__global__ void gather_kernel(const float* __restrict__ X, float* __restrict__ out,
                              int N) {
    int e = blockIdx.x * blockDim.x + threadIdx.x;
    int i = e >> 7, d = e & 127;
    int j = g_bestidx[i];
    float q = g_newmean[(size_t)j * D + d];
    float x = X[e];
    out[e] = x + (q - x);
    float df = x - q;
    float tot = blockReduceSum(df * df);
    if (threadIdx.x == 0) atomicAdd(&g_scalars[1], tot);
}
__global__ void final_kernel(float* __restrict__ out, int N, long long out_size) {
    int i = blockIdx.x * blockDim.x + threadIdx.x;
    long long base = (long long)N * D;
    if (i < N && base + i < out_size) out[base + i] = (float)g_bestidx[i];
    if (i == 0 && base + N < out_size)
        out[base + N] = 0.25f * g_scalars[1] / (float)((long long)N * D);
}

// ---------------- launch ------------------------------------------------------
extern "C" void kernel_launch(void* const* d_in, const int* in_sizes, int n_in,
                              void* d_out, int out_size) {
    const float* X     = (const float*)d_in[0];
    const float* E     = (const float*)d_in[1];
    const float* csize = (const float*)d_in[2];
    const float* csum  = (const float*)d_in[3];
    float* out = (float*)d_out;

    int K = in_sizes[2];
    int N = in_sizes[0] / D;

    cudaFuncSetAttribute(argmin_approx, cudaFuncAttributeMaxDynamicSharedMemorySize,
                         S1_SMEM);
    cudaFuncSetAttribute(argmin_exact, cudaFuncAttributeMaxDynamicSharedMemorySize,
                         SMEM_SZ);

    zero_kernel<<<(KPAD * D + 255) / 256, 256>>>();
    halfnorm_kernel<<<(KPAD * 32 + 255) / 256, 256>>>(E, K);
    norms_x<<<(NMAX * 32 + 255) / 256, 256>>>(X);
    prep_a<<<((NMAX / 16) * 256 + 255) / 256, 256>>>(X);
    prep_b<<<((KPAD / 8) * 256 + 255) / 256, 256>>>(E, K);
    argmin_approx<<<(N / 128) * NSEG1, 512, S1_SMEM>>>();
    reduce_rows<<<(N * 32 + 255) / 256, 256>>>();
    prep_a2<<<NMAX / 16, 256>>>(X);
    argmin_exact<<<(N / 128) * NSEG2, 512, SMEM_SZ>>>();
    scatter_kernel<<<(N * 32 + 255) / 256, 256>>>(X, N);
    size_kernel<<<(K + 255) / 256, 256>>>(csize, K);
    mean_kernel<<<(K * D + 255) / 256, 256>>>(csum, K);
    gather_kernel<<<(N * D) / 256, 256>>>(X, out, N);
    final_kernel<<<(N + 255) / 256, 256>>>(out, N, (long long)out_size);
}